// round 1
// baseline (speedup 1.0000x reference)
#include <cuda_runtime.h>
#include <math.h>

// Problem constants (fixed shapes from setup_inputs)
#define BSZ 32
#define TT  50
#define CC  80
#define AA  85          // 5 + C
#define HH  76
#define WW  76
#define HWX (HH*WW)     // 5776
#define SIGMA_F 8.0f
#define THR 0.5f

// ---------------- device scratch (no allocations allowed) ----------------
__device__ int    g_neff[BSZ];
__device__ float  g_gx1[BSZ*TT], g_gy1[BSZ*TT], g_gx2[BSZ*TT], g_gy2[BSZ*TT], g_area[BSZ*TT];
__device__ int    g_cell[BSZ*TT];
__device__ float  g_tx[BSZ*TT], g_ty[BSZ*TT], g_tw[BSZ*TT], g_th[BSZ*TT], g_scale[BSZ*TT];
__device__ int    g_cls[BSZ*TT];
__device__ double g_acc[7];   // Sx, Sy, Sw, Sh, Sconf_obj, Sconf_noobj, Scls
__device__ int    g_nobj;

// ---------------- math helpers matching the reference exactly ----------------
__device__ __forceinline__ float sigmoidf_(float v) {
    return 1.0f / (1.0f + expf(-v));
}
// torch-BCE clamped log: clip(log(clip(p,1e-12,1)), -100, 0)
__device__ __forceinline__ float clogf_(float p) {
    p = fminf(fmaxf(p, 1e-12f), 1.0f);
    float l = logf(p);
    return fminf(fmaxf(l, -100.0f), 0.0f);
}
__device__ __forceinline__ float bcef_(float p, float t) {
    return -(t * clogf_(p) + (1.0f - t) * clogf_(1.0f - p));
}
__device__ __forceinline__ float sl1f_(float a, float b) {
    float d = fabsf(a - b);
    return (d < 1.0f) ? 0.5f * d * d : d - 0.5f;
}

// ---------------- kernel 1: per-batch target prep (serial dedup) ----------------
__global__ void yolo_prep(const float* __restrict__ targets) {
    int b = threadIdx.x;
    if (b < 7) g_acc[b] = 0.0;
    if (b == 0) g_nobj = 0;
    __syncthreads();
    if (b >= BSZ) return;

    int vcells[TT];   // cells of earlier VALID targets (dup check uses valid, not eff)
    int nv = 0;
    int ne = 0;
    for (int t = 0; t < TT; t++) {
        const float* tg = targets + ((size_t)b * TT + t) * 5;
        float t0 = tg[0], t1 = tg[1], t2 = tg[2], t3 = tg[3], t4 = tg[4];
        float s = t0 + t1 + t2 + t3 + t4;
        bool valid = (s != 0.0f);

        float gx = t1 * (float)WW;
        float gy = t2 * (float)HH;
        float gw = t3 * (float)WW;
        float gh = t4 * (float)HH;
        int gi = min(max((int)gx, 0), WW - 1);
        int gj = min(max((int)gy, 0), HH - 1);
        int cell = gj * WW + gi;

        bool dup = false;
        for (int k = 0; k < nv; k++) if (vcells[k] == cell) dup = true;
        if (valid) vcells[nv++] = cell;

        if (valid && !dup) {
            int idx = b * TT + ne;
            g_gx1[idx]  = gx - gw * 0.5f;
            g_gy1[idx]  = gy - gh * 0.5f;
            g_gx2[idx]  = gx + gw * 0.5f;
            g_gy2[idx]  = gy + gh * 0.5f;
            g_area[idx] = gw * gh;
            g_cell[idx] = cell;
            g_tx[idx]   = gx - (float)gi;
            g_ty[idx]   = gy - (float)gj;
            g_tw[idx]   = logf(gw / SIGMA_F + 1e-16f);
            g_th[idx]   = logf(gh / SIGMA_F + 1e-16f);
            g_scale[idx]= 2.0f - t3 * t4;
            g_cls[idx]  = min(max((int)t0, 0), CC - 1);
            ne++;
        }
    }
    g_neff[b] = ne;
    atomicAdd(&g_nobj, ne);
}

// ---------------- kernel 2: full-grid loss pass ----------------
__global__ __launch_bounds__(256) void yolo_grid(const float* __restrict__ inp) {
    __shared__ float s_gx1[TT], s_gy1[TT], s_gx2[TT], s_gy2[TT], s_area[TT];
    __shared__ int   s_cell[TT];
    __shared__ float s_tx[TT], s_ty[TT], s_tw[TT], s_th[TT], s_scale[TT];
    __shared__ int   s_cls[TT];
    __shared__ float s_acc[7];
    __shared__ int   s_ne;

    const int b   = blockIdx.y;
    const int tid = threadIdx.x;

    if (tid == 0) s_ne = g_neff[b];
    if (tid < 7)  s_acc[tid] = 0.0f;
    __syncthreads();
    const int ne = s_ne;
    if (tid < ne) {
        int idx = b * TT + tid;
        s_gx1[tid]   = g_gx1[idx];
        s_gy1[tid]   = g_gy1[idx];
        s_gx2[tid]   = g_gx2[idx];
        s_gy2[tid]   = g_gy2[idx];
        s_area[tid]  = g_area[idx];
        s_cell[tid]  = g_cell[idx];
        s_tx[tid]    = g_tx[idx];
        s_ty[tid]    = g_ty[idx];
        s_tw[tid]    = g_tw[idx];
        s_th[tid]    = g_th[idx];
        s_scale[tid] = g_scale[idx];
        s_cls[tid]   = g_cls[idx];
    }
    __syncthreads();

    float acc0 = 0.f, acc1 = 0.f, acc2 = 0.f, acc3 = 0.f, acc4 = 0.f, acc5 = 0.f, acc6 = 0.f;

    const int cell = blockIdx.x * blockDim.x + tid;
    if (cell < HWX) {
        const float* base = inp + (size_t)b * AA * HWX + cell;
        float v0 = base[0];
        float v1 = base[(size_t)1 * HWX];
        float v2 = base[(size_t)2 * HWX];
        float v3 = base[(size_t)3 * HWX];
        float v4 = base[(size_t)4 * HWX];

        float x    = sigmoidf_(v0);
        float y    = sigmoidf_(v1);
        float conf = sigmoidf_(v4);

        int i = cell % WW;
        int j = cell / WW;
        float px = x + (float)i;
        float py = y + (float)j;
        float pw = expf(v2) * SIGMA_F;
        float ph = expf(v3) * SIGMA_F;
        float px1 = px - pw * 0.5f, px2 = px + pw * 0.5f;
        float py1 = py - ph * 0.5f, py2 = py + ph * 0.5f;
        float parea = pw * ph;

        bool ignore = false;
        int match = -1;
        #pragma unroll 4
        for (int e = 0; e < ne; e++) {
            float iw = fminf(s_gx2[e], px2) - fmaxf(s_gx1[e], px1);
            float ih = fminf(s_gy2[e], py2) - fmaxf(s_gy1[e], py1);
            iw = fmaxf(iw, 0.0f);
            ih = fmaxf(ih, 0.0f);
            float inter = iw * ih;
            float iou = inter / (s_area[e] + parea - inter + 1e-16f);
            if (iou >= THR) ignore = true;
            if (s_cell[e] == cell) match = e;
        }

        if (match >= 0) {
            float sc = s_scale[match];
            acc0 = sc * bcef_(x, s_tx[match]);
            acc1 = sc * bcef_(y, s_ty[match]);
            acc2 = sc * sl1f_(v2, s_tw[match]);
            acc3 = sc * sl1f_(v3, s_th[match]);
            acc4 = -clogf_(conf);           // bce(conf,1) at mask cells
            int cls = s_cls[match];
            float scl = 0.0f;
            for (int c = 0; c < CC; c++) {
                float p = sigmoidf_(base[(size_t)(5 + c) * HWX]);
                scl += (c == cls) ? -clogf_(p) : -clogf_(1.0f - p);
            }
            acc6 = scl;
        } else if (!ignore) {
            acc5 = -clogf_(1.0f - conf);    // noobj term
        }
    }

    // warp shuffle reduce, then shared atomics, then one double atomic per block
    float vals[7] = {acc0, acc1, acc2, acc3, acc4, acc5, acc6};
    #pragma unroll
    for (int k = 0; k < 7; k++) {
        float v = vals[k];
        #pragma unroll
        for (int o = 16; o > 0; o >>= 1) v += __shfl_down_sync(0xffffffffu, v, o);
        if ((tid & 31) == 0 && v != 0.0f) atomicAdd(&s_acc[k], v);
    }
    __syncthreads();
    if (tid < 7 && s_acc[tid] != 0.0f) atomicAdd(&g_acc[tid], (double)s_acc[tid]);
}

// ---------------- kernel 3: finalize ----------------
__global__ void yolo_fin(float* __restrict__ out) {
    double n   = (double)g_nobj;
    double inv = 1.0 / n;
    double lx = g_acc[0] * inv;
    double ly = g_acc[1] * inv;
    double lw = g_acc[2] * inv;
    double lh = g_acc[3] * inv;
    double lconf = (g_acc[4] + 0.5 * g_acc[5]) * inv;
    double lcls  = (g_nobj > 0) ? g_acc[6] * inv : 0.0;   // sum(tcls) == n_obj
    double loss = lx + ly + lw + lh + lconf + lcls;
    out[0] = (float)loss;
    out[1] = (float)lx;
    out[2] = (float)ly;
    out[3] = (float)lw;
    out[4] = (float)lh;
    out[5] = (float)lconf;
    out[6] = (float)lcls;
}

// ---------------- launch ----------------
extern "C" void kernel_launch(void* const* d_in, const int* in_sizes, int n_in,
                              void* d_out, int out_size) {
    const float* inp     = (const float*)d_in[0];   // [32, 85, 76, 76]
    const float* targets = (const float*)d_in[1];   // [32, 50, 5]
    float* out = (float*)d_out;

    yolo_prep<<<1, 32>>>(targets);

    dim3 grid((HWX + 255) / 256, BSZ);
    yolo_grid<<<grid, 256>>>(inp);

    yolo_fin<<<1, 1>>>(out);
}

// round 2
// speedup vs baseline: 2.2747x; 2.2747x over previous
#include <cuda_runtime.h>
#include <math.h>

// Fixed shapes from setup_inputs
#define BSZ 32
#define TT  50
#define CC  80
#define AA  85          // 5 + C
#define HH  76
#define WW  76
#define HWX (HH*WW)     // 5776
#define SIGMA_F 8.0f

#define BLK 256
#define GX  ((HWX + BLK - 1) / BLK)   // 23
#define NBLOCKS (GX * BSZ)            // 736

// ---------------- device scratch (statics are zero-initialized) ----------------
__device__ double g_acc[7];     // Sx, Sy, Sw, Sh, Sconf_obj, Sconf_noobj, Scls
__device__ int    g_neff[BSZ];
__device__ unsigned int g_done; // arrival counter (reset by finalizer each run)

// ---------------- math helpers matching the reference exactly ----------------
__device__ __forceinline__ float sigmoidf_(float v) {
    return 1.0f / (1.0f + expf(-v));
}
// torch-BCE clamped log: clip(log(clip(p,1e-12,1)), -100, 0)
__device__ __forceinline__ float clogf_(float p) {
    p = fminf(fmaxf(p, 1e-12f), 1.0f);
    float l = logf(p);
    return fminf(fmaxf(l, -100.0f), 0.0f);
}
__device__ __forceinline__ float bcef_(float p, float t) {
    return -(t * clogf_(p) + (1.0f - t) * clogf_(1.0f - p));
}
__device__ __forceinline__ float sl1f_(float a, float b) {
    float d = fabsf(a - b);
    return (d < 1.0f) ? 0.5f * d * d : d - 0.5f;
}

// ---------------- single fused kernel ----------------
__global__ __launch_bounds__(BLK) void yolo_fused(const float* __restrict__ inp,
                                                  const float* __restrict__ targets,
                                                  float* __restrict__ out) {
    // per-target data (effective, compacted)
    __shared__ float s_gx1[TT], s_gy1[TT], s_gx2[TT], s_gy2[TT], s_area[TT];
    __shared__ int   s_cell[TT];
    __shared__ float s_tx[TT], s_ty[TT], s_tw[TT], s_th[TT], s_scale[TT];
    __shared__ int   s_cls[TT];
    // prep temporaries
    __shared__ int   s_vcell[TT];
    __shared__ int   s_val[TT];
    __shared__ int   s_ne;
    __shared__ float s_acc[7];

    const int b   = blockIdx.y;
    const int tid = threadIdx.x;

    if (tid == 0) s_ne = 0;
    if (tid < 7)  s_acc[tid] = 0.0f;

    // ---- inline parallel target prep (threads 0..TT-1) ----
    float gx = 0.f, gy = 0.f, gw = 0.f, gh = 0.f, t0 = 0.f, t3 = 0.f, t4 = 0.f;
    int gi = 0, gj = 0;
    if (tid < TT) {
        const float* tg = targets + ((size_t)b * TT + tid) * 5;
        t0 = tg[0];
        float t1 = tg[1], t2 = tg[2];
        t3 = tg[3]; t4 = tg[4];
        bool valid = ((t0 + t1 + t2 + t3 + t4) != 0.0f);
        gx = t1 * (float)WW;
        gy = t2 * (float)HH;
        gw = t3 * (float)WW;
        gh = t4 * (float)HH;
        gi = min(max((int)gx, 0), WW - 1);
        gj = min(max((int)gy, 0), HH - 1);
        s_vcell[tid] = gj * WW + gi;
        s_val[tid]   = valid ? 1 : 0;
    }
    __syncthreads();
    if (tid < TT && s_val[tid]) {
        const int mycell = s_vcell[tid];
        bool dup = false;
        for (int k = 0; k < tid; k++)
            dup |= (s_val[k] && (s_vcell[k] == mycell));
        if (!dup) {
            int pos = atomicAdd(&s_ne, 1);
            s_gx1[pos]  = gx - gw * 0.5f;
            s_gy1[pos]  = gy - gh * 0.5f;
            s_gx2[pos]  = gx + gw * 0.5f;
            s_gy2[pos]  = gy + gh * 0.5f;
            s_area[pos] = gw * gh;
            s_cell[pos] = mycell;
            s_tx[pos]   = gx - (float)gi;
            s_ty[pos]   = gy - (float)gj;
            s_tw[pos]   = logf(gw / SIGMA_F + 1e-16f);
            s_th[pos]   = logf(gh / SIGMA_F + 1e-16f);
            s_scale[pos]= 2.0f - t3 * t4;
            s_cls[pos]  = min(max((int)t0, 0), CC - 1);
        }
    }
    __syncthreads();
    const int ne = s_ne;
    if (blockIdx.x == 0 && tid == 0) g_neff[b] = ne;

    // ---- per-cell loss ----
    float acc0 = 0.f, acc1 = 0.f, acc2 = 0.f, acc3 = 0.f, acc4 = 0.f, acc5 = 0.f, acc6 = 0.f;

    const int cell = blockIdx.x * BLK + tid;
    if (cell < HWX) {
        const float* base = inp + (size_t)b * AA * HWX + cell;
        float v0 = base[0];
        float v1 = base[(size_t)1 * HWX];
        float v2 = base[(size_t)2 * HWX];
        float v3 = base[(size_t)3 * HWX];
        float v4 = base[(size_t)4 * HWX];

        float x    = sigmoidf_(v0);
        float y    = sigmoidf_(v1);
        float conf = sigmoidf_(v4);

        int i = cell % WW;
        int j = cell / WW;
        float px = x + (float)i;
        float py = y + (float)j;
        float pw = expf(v2) * SIGMA_F;
        float ph = expf(v3) * SIGMA_F;
        float px1 = px - pw * 0.5f, px2 = px + pw * 0.5f;
        float py1 = py - ph * 0.5f, py2 = py + ph * 0.5f;
        float parea = pw * ph;

        bool ignore = false;
        int match = -1;
        #pragma unroll 5
        for (int e = 0; e < ne; e++) {
            float iw = fminf(s_gx2[e], px2) - fmaxf(s_gx1[e], px1);
            float ih = fminf(s_gy2[e], py2) - fmaxf(s_gy1[e], py1);
            iw = fmaxf(iw, 0.0f);
            ih = fmaxf(ih, 0.0f);
            float inter = iw * ih;
            // iou >= 0.5  <=>  2*inter >= union   (union = ga + pa - inter + 1e-16)
            ignore |= (2.0f * inter >= (s_area[e] + parea - inter + 1e-16f));
            if (s_cell[e] == cell) match = e;
        }

        if (match >= 0) {
            float sc = s_scale[match];
            acc0 = sc * bcef_(x, s_tx[match]);
            acc1 = sc * bcef_(y, s_ty[match]);
            acc2 = sc * sl1f_(v2, s_tw[match]);
            acc3 = sc * sl1f_(v3, s_th[match]);
            acc4 = -clogf_(conf);                  // bce(conf,1) at mask cells
            int cls = s_cls[match];
            float scl = 0.0f;
            for (int c = 0; c < CC; c++) {
                float p = sigmoidf_(base[(size_t)(5 + c) * HWX]);
                scl += (c == cls) ? -clogf_(p) : -clogf_(1.0f - p);
            }
            acc6 = scl;
        } else if (!ignore) {
            acc5 = -clogf_(1.0f - conf);           // noobj term
        }
    }

    // ---- block reduce: warp shuffle -> shared float atomics -> global double atomic ----
    float vals[7] = {acc0, acc1, acc2, acc3, acc4, acc5, acc6};
    #pragma unroll
    for (int k = 0; k < 7; k++) {
        float v = vals[k];
        #pragma unroll
        for (int o = 16; o > 0; o >>= 1) v += __shfl_down_sync(0xffffffffu, v, o);
        if ((tid & 31) == 0 && v != 0.0f) atomicAdd(&s_acc[k], v);
    }
    __syncthreads();
    if (tid < 7 && s_acc[tid] != 0.0f) atomicAdd(&g_acc[tid], (double)s_acc[tid]);

    // ---- fused finalize: last block to arrive computes the outputs ----
    __shared__ bool s_last;
    if (tid == 0) {
        __threadfence();
        unsigned int ticket = atomicAdd(&g_done, 1u);
        s_last = (ticket == (unsigned int)(NBLOCKS - 1));
    }
    __syncthreads();
    if (s_last && tid == 0) {
        __threadfence();
        volatile double* acc = g_acc;
        int nobj = 0;
        for (int k = 0; k < BSZ; k++) nobj += g_neff[k];
        double inv = 1.0 / (double)nobj;
        double lx = acc[0] * inv;
        double ly = acc[1] * inv;
        double lw = acc[2] * inv;
        double lh = acc[3] * inv;
        double lconf = (acc[4] + 0.5 * acc[5]) * inv;
        double lcls  = (nobj > 0) ? acc[6] * inv : 0.0;  // sum(tcls) == n_obj
        double loss = lx + ly + lw + lh + lconf + lcls;
        out[0] = (float)loss;
        out[1] = (float)lx;
        out[2] = (float)ly;
        out[3] = (float)lw;
        out[4] = (float)lh;
        out[5] = (float)lconf;
        out[6] = (float)lcls;
        // reset state for the next graph replay
        for (int k = 0; k < 7; k++) g_acc[k] = 0.0;
        g_done = 0u;
    }
}

// ---------------- launch ----------------
extern "C" void kernel_launch(void* const* d_in, const int* in_sizes, int n_in,
                              void* d_out, int out_size) {
    const float* inp     = (const float*)d_in[0];   // [32, 85, 76, 76]
    const float* targets = (const float*)d_in[1];   // [32, 50, 5]
    float* out = (float*)d_out;

    dim3 grid(GX, BSZ);
    yolo_fused<<<grid, BLK>>>(inp, targets, out);
}

// round 3
// speedup vs baseline: 2.4918x; 1.0955x over previous
#include <cuda_runtime.h>
#include <math.h>

// Fixed shapes from setup_inputs
#define BSZ 32
#define TT  50
#define CC  80
#define AA  85          // 5 + C
#define HH  76
#define WW  76
#define HWX (HH*WW)     // 5776
#define SIGMA_F 8.0f

#define BLK  256
#define ILP  4
#define CHUNK (BLK*ILP)                 // 1024 cells per block
#define GX   ((HWX + CHUNK - 1) / CHUNK) // 6
#define NBLOCKS (GX * BSZ)               // 192

// ---------------- device scratch ----------------
__device__ double g_acc[7];     // Sx, Sy, Sw, Sh, Sconf_obj, Sconf_noobj, Scls
__device__ int    g_neff[BSZ];
__device__ unsigned int g_done;

// ---------------- fast math helpers (tolerance 1e-3; these are ~1e-6) ----------------
__device__ __forceinline__ float sigmoidf_(float v) {
    return __fdividef(1.0f, 1.0f + __expf(-v));
}
// torch-BCE clamped log: clip(log(clip(p,1e-12,1)), -100, 0)
__device__ __forceinline__ float clogf_(float p) {
    p = fminf(fmaxf(p, 1e-12f), 1.0f);
    float l = __logf(p);
    return fminf(fmaxf(l, -100.0f), 0.0f);
}
__device__ __forceinline__ float bcef_(float p, float t) {
    return -(t * clogf_(p) + (1.0f - t) * clogf_(1.0f - p));
}
__device__ __forceinline__ float sl1f_(float a, float b) {
    float d = fabsf(a - b);
    return (d < 1.0f) ? 0.5f * d * d : d - 0.5f;
}

// ---------------- single fused kernel ----------------
__global__ __launch_bounds__(BLK) void yolo_fused(const float* __restrict__ inp,
                                                  const float* __restrict__ targets,
                                                  float* __restrict__ out) {
    __shared__ float s_gx1[TT], s_gy1[TT], s_gx2[TT], s_gy2[TT], s_area[TT];
    __shared__ int   s_cell[TT];
    __shared__ float s_tx[TT], s_ty[TT], s_tw[TT], s_th[TT], s_scale[TT];
    __shared__ int   s_cls[TT];
    __shared__ int   s_vcell[TT];
    __shared__ int   s_val[TT];
    __shared__ int   s_ne;
    __shared__ float s_acc[7];

    const int b   = blockIdx.y;
    const int tid = threadIdx.x;

    if (tid == 0) s_ne = 0;
    if (tid < 7)  s_acc[tid] = 0.0f;

    // ---- inline parallel target prep (threads 0..TT-1) ----
    float gx = 0.f, gy = 0.f, gw = 0.f, gh = 0.f, t0 = 0.f, t3 = 0.f, t4 = 0.f;
    int gi = 0, gj = 0;
    if (tid < TT) {
        const float* tg = targets + ((size_t)b * TT + tid) * 5;
        t0 = tg[0];
        float t1 = tg[1], t2 = tg[2];
        t3 = tg[3]; t4 = tg[4];
        bool valid = ((t0 + t1 + t2 + t3 + t4) != 0.0f);
        gx = t1 * (float)WW;
        gy = t2 * (float)HH;
        gw = t3 * (float)WW;
        gh = t4 * (float)HH;
        gi = min(max((int)gx, 0), WW - 1);
        gj = min(max((int)gy, 0), HH - 1);
        s_vcell[tid] = gj * WW + gi;
        s_val[tid]   = valid ? 1 : 0;
    }
    __syncthreads();
    if (tid < TT && s_val[tid]) {
        const int mycell = s_vcell[tid];
        bool dup = false;
        for (int k = 0; k < tid; k++)
            dup |= (s_val[k] && (s_vcell[k] == mycell));
        if (!dup) {
            int pos = atomicAdd(&s_ne, 1);
            s_gx1[pos]  = gx - gw * 0.5f;
            s_gy1[pos]  = gy - gh * 0.5f;
            s_gx2[pos]  = gx + gw * 0.5f;
            s_gy2[pos]  = gy + gh * 0.5f;
            s_area[pos] = gw * gh;
            s_cell[pos] = mycell;
            s_tx[pos]   = gx - (float)gi;
            s_ty[pos]   = gy - (float)gj;
            s_tw[pos]   = __logf(gw / SIGMA_F + 1e-16f);
            s_th[pos]   = __logf(gh / SIGMA_F + 1e-16f);
            s_scale[pos]= 2.0f - t3 * t4;
            s_cls[pos]  = min(max((int)t0, 0), CC - 1);
        }
    }
    __syncthreads();
    const int ne = s_ne;
    if (blockIdx.x == 0 && tid == 0) g_neff[b] = ne;

    // ---- per-cell loss: ILP over 4 cells per thread ----
    const float* bbase = inp + (size_t)b * AA * HWX;
    const int c0 = blockIdx.x * CHUNK + tid;

    int   cellid[ILP];
    bool  cvalid[ILP];
    float v0a[ILP], v1a[ILP], v2a[ILP], v3a[ILP], v4a[ILP];
    float px1[ILP], px2[ILP], py1[ILP], py2[ILP], pa[ILP];

    #pragma unroll
    for (int u = 0; u < ILP; u++) {
        int c = c0 + u * BLK;
        cellid[u] = c;
        bool ok = (c < HWX);
        cvalid[u] = ok;
        int cc = ok ? c : 0;
        v0a[u] = bbase[cc];
        v1a[u] = bbase[(size_t)1 * HWX + cc];
        v2a[u] = bbase[(size_t)2 * HWX + cc];
        v3a[u] = bbase[(size_t)3 * HWX + cc];
        v4a[u] = bbase[(size_t)4 * HWX + cc];

        float xs = sigmoidf_(v0a[u]);
        float ys = sigmoidf_(v1a[u]);
        int i = cc % WW;
        int j = cc / WW;
        float px = xs + (float)i;
        float py = ys + (float)j;
        float pw = __expf(v2a[u]) * SIGMA_F;
        float ph = __expf(v3a[u]) * SIGMA_F;
        px1[u] = px - pw * 0.5f; px2[u] = px + pw * 0.5f;
        py1[u] = py - ph * 0.5f; py2[u] = py + ph * 0.5f;
        pa[u]  = pw * ph;
    }

    bool ign[ILP];
    int  match[ILP];
    #pragma unroll
    for (int u = 0; u < ILP; u++) { ign[u] = false; match[u] = -1; }

    for (int e = 0; e < ne; e++) {
        float egx1 = s_gx1[e], egy1 = s_gy1[e];
        float egx2 = s_gx2[e], egy2 = s_gy2[e];
        float ega  = s_area[e];
        int   ecl  = s_cell[e];
        #pragma unroll
        for (int u = 0; u < ILP; u++) {
            float iw = fminf(egx2, px2[u]) - fmaxf(egx1, px1[u]);
            float ih = fminf(egy2, py2[u]) - fmaxf(egy1, py1[u]);
            iw = fmaxf(iw, 0.0f);
            ih = fmaxf(ih, 0.0f);
            float inter = iw * ih;
            // iou >= 0.5  <=>  2*inter >= ga + pa - inter + 1e-16
            ign[u] |= (2.0f * inter >= (ega + pa[u] - inter + 1e-16f));
            if (ecl == cellid[u]) match[u] = e;
        }
    }

    float acc0 = 0.f, acc1 = 0.f, acc2 = 0.f, acc3 = 0.f, acc4 = 0.f, acc5 = 0.f, acc6 = 0.f;

    #pragma unroll
    for (int u = 0; u < ILP; u++) {
        if (!cvalid[u]) continue;
        float conf = sigmoidf_(v4a[u]);
        int m = match[u];
        if (m >= 0) {
            float sc = s_scale[m];
            float xs = sigmoidf_(v0a[u]);
            float ys = sigmoidf_(v1a[u]);
            acc0 += sc * bcef_(xs, s_tx[m]);
            acc1 += sc * bcef_(ys, s_ty[m]);
            acc2 += sc * sl1f_(v2a[u], s_tw[m]);
            acc3 += sc * sl1f_(v3a[u], s_th[m]);
            acc4 += -clogf_(conf);
            int cls = s_cls[m];
            float scl = 0.0f;
            const float* cb = bbase + cellid[u];
            for (int c = 0; c < CC; c++) {
                float p = sigmoidf_(cb[(size_t)(5 + c) * HWX]);
                scl += (c == cls) ? -clogf_(p) : -clogf_(1.0f - p);
            }
            acc6 += scl;
        } else if (!ign[u]) {
            acc5 += -clogf_(1.0f - conf);   // noobj term
        }
    }

    // ---- block reduce ----
    float vals[7] = {acc0, acc1, acc2, acc3, acc4, acc5, acc6};
    #pragma unroll
    for (int k = 0; k < 7; k++) {
        float v = vals[k];
        #pragma unroll
        for (int o = 16; o > 0; o >>= 1) v += __shfl_down_sync(0xffffffffu, v, o);
        if ((tid & 31) == 0 && v != 0.0f) atomicAdd(&s_acc[k], v);
    }
    __syncthreads();
    if (tid < 7 && s_acc[tid] != 0.0f) atomicAdd(&g_acc[tid], (double)s_acc[tid]);

    // ---- fused finalize: last block computes outputs, resets state ----
    __shared__ bool s_last;
    if (tid == 0) {
        __threadfence();
        unsigned int ticket = atomicAdd(&g_done, 1u);
        s_last = (ticket == (unsigned int)(NBLOCKS - 1));
    }
    __syncthreads();
    if (s_last && tid == 0) {
        __threadfence();
        volatile double* acc = g_acc;
        int nobj = 0;
        for (int k = 0; k < BSZ; k++) nobj += g_neff[k];
        double inv = 1.0 / (double)nobj;
        double lx = acc[0] * inv;
        double ly = acc[1] * inv;
        double lw = acc[2] * inv;
        double lh = acc[3] * inv;
        double lconf = (acc[4] + 0.5 * acc[5]) * inv;
        double lcls  = (nobj > 0) ? acc[6] * inv : 0.0;  // sum(tcls) == n_obj
        double loss = lx + ly + lw + lh + lconf + lcls;
        out[0] = (float)loss;
        out[1] = (float)lx;
        out[2] = (float)ly;
        out[3] = (float)lw;
        out[4] = (float)lh;
        out[5] = (float)lconf;
        out[6] = (float)lcls;
        for (int k = 0; k < 7; k++) g_acc[k] = 0.0;
        g_done = 0u;
    }
}

// ---------------- launch ----------------
extern "C" void kernel_launch(void* const* d_in, const int* in_sizes, int n_in,
                              void* d_out, int out_size) {
    const float* inp     = (const float*)d_in[0];   // [32, 85, 76, 76]
    const float* targets = (const float*)d_in[1];   // [32, 50, 5]
    float* out = (float*)d_out;

    dim3 grid(GX, BSZ);
    yolo_fused<<<grid, BLK>>>(inp, targets, out);
}